// round 17
// baseline (speedup 1.0000x reference)
#include <cuda_runtime.h>
#include <cuda_bf16.h>
#include <cstdint>

typedef unsigned int uint;

constexpr int B    = 512;
constexpr int T    = 2048;
constexpr int H    = 64;
constexpr int NB   = 4;
constexpr int NBLK = B / NB;   // 128 blocks, 1/SM
constexpr int NTHR = 160;      // 4 mma warps + 1 layer-2 warp

// dynamic smem layout (bytes)
constexpr int OFF_XS  = 0;                          // float [T][NB]        32KB
constexpr int OFF_ALO = OFF_XS + T * NB * 4;        // uint [4w][4q][4kt][4e][32] 32KB
constexpr int OFF_HBH = OFF_ALO + 4 * 4 * 4 * 4 * 32 * 4;  // bf16 [2][8][72]
constexpr int OFF_HBL = OFF_HBH + 2 * 8 * 72 * 2;
constexpr int OFF_C1B = OFF_HBL + 2 * 8 * 72 * 2;   // float [2][NB][H]
constexpr int SMEM_SZ = OFF_C1B + 2 * NB * H * 4;

__device__ __forceinline__ float fsigm(float x) {
    return __fdividef(1.f, 1.f + __expf(-x));
}
__device__ __forceinline__ float ftanh(float x) {
    return __fdividef(2.f, 1.f + __expf(-2.f * x)) - 1.f;
}
__device__ __forceinline__ uint pack_bf2(float e0, float e1) {
    unsigned short u0 = __bfloat16_as_ushort(__float2bfloat16(e0));
    unsigned short u1 = __bfloat16_as_ushort(__float2bfloat16(e1));
    return (uint)u0 | ((uint)u1 << 16);
}
__device__ __forceinline__ void mma16816(float& c0, float& c1, float& c2, float& c3,
                                         uint a0, uint a1, uint a2, uint a3,
                                         uint b0, uint b1) {
    asm volatile(
        "mma.sync.aligned.m16n8k16.row.col.f32.bf16.bf16.f32 "
        "{%0,%1,%2,%3}, {%4,%5,%6,%7}, {%8,%9}, {%0,%1,%2,%3};"
        : "+f"(c0), "+f"(c1), "+f"(c2), "+f"(c3)
        : "r"(a0), "r"(a1), "r"(a2), "r"(a3), "r"(b0), "r"(b1));
}

__global__ __launch_bounds__(NTHR, 1)
void lstm2_kernel(const float* __restrict__ x,
                  const float* __restrict__ Wih1,
                  const float* __restrict__ Whh1,
                  const float* __restrict__ bih1,
                  const float* __restrict__ bhh1,
                  const float* __restrict__ Wih2,
                  const float* __restrict__ Whh2,
                  const float* __restrict__ bih2,
                  const float* __restrict__ bhh2,
                  float* __restrict__ out)
{
    extern __shared__ __align__(16) char smem[];
    float*         xs   = (float*)(smem + OFF_XS);
    uint*          aloS = (uint*)(smem + OFF_ALO);
    __nv_bfloat16* hbh  = (__nv_bfloat16*)(smem + OFF_HBH);
    __nv_bfloat16* hbl  = (__nv_bfloat16*)(smem + OFF_HBL);
    float*         c1b  = (float*)(smem + OFF_C1B);

    const int tid  = threadIdx.x;
    const int wid  = tid >> 5;
    const int lane = tid & 31;
    const int b0g  = blockIdx.x * NB;

    // ---- one-time preload ----
    for (int bl = 0; bl < NB; bl++)
        for (int t = tid; t < T; t += NTHR)
            xs[t * NB + bl] = x[(b0g + bl) * T + t];
    for (int i = tid; i < 2 * 8 * 72; i += NTHR) {
        hbh[i] = __float2bfloat16(0.f);
        hbl[i] = __float2bfloat16(0.f);
    }

    const bool is_gate = wid < 4;
    const int  lq = lane >> 2;   // fragment group (unit-low / B-col)
    const int  m  = lane & 3;    // fragment thread-in-group
    const int  u0 = wid * 16 + lq;
    const int  u1 = u0 + 8;
    const bool real = (m < 2);   // C cols 2m,2m+1 are real batches iff m<2

    // A-hi fragments in registers; A-lo fragments go to smem (reload per step)
    uint Ahi[4][4][4];
    float wiA[4][2], bsA[4][2];
    float cst[4] = {0.f, 0.f, 0.f, 0.f};  // c1 state: (u0,b0),(u0,b1),(u1,b0),(u1,b1)
    if (is_gate) {
        #pragma unroll
        for (int q = 0; q < 4; q++) {
            #pragma unroll
            for (int kt = 0; kt < 4; kt++) {
                const int r0 = q * 64 + wid * 16 + lq;
                const int c0 = kt * 16 + 2 * m;
                #pragma unroll
                for (int e = 0; e < 4; e++) {
                    const int r = r0 + (e & 1) * 8;
                    const int c = c0 + (e >> 1) * 8;
                    float v0 = Whh1[r * H + c];
                    float v1 = Whh1[r * H + c + 1];
                    __nv_bfloat16 h0 = __float2bfloat16(v0);
                    __nv_bfloat16 h1 = __float2bfloat16(v1);
                    Ahi[q][kt][e] = ((uint)__bfloat16_as_ushort(h1) << 16) |
                                    __bfloat16_as_ushort(h0);
                    aloS[(((wid * 4 + q) * 4 + kt) * 4 + e) * 32 + lane] =
                        pack_bf2(v0 - __bfloat162float(h0),
                                 v1 - __bfloat162float(h1));
                }
            }
            wiA[q][0] = Wih1[q * H + u0];
            wiA[q][1] = Wih1[q * H + u1];
            bsA[q][0] = bih1[q * H + u0] + bhh1[q * H + u0];
            bsA[q][1] = bih1[q * H + u1] + bhh1[q * H + u1];
        }
    }

    // layer-2 warp (wid 4): lane: bl2=lane>>3, qq=(lane>>1)&3, koff=(lane&1)*32
    float w2[32];
    float whh2q = 0.f, b2q = 0.f, h2v = 0.f, c2v = 0.f;
    int bl2 = 0, koff = 0;
    if (!is_gate) {
        bl2  = lane >> 3;
        const int qq = (lane >> 1) & 3;
        koff = (lane & 1) * 32;
        #pragma unroll
        for (int jj = 0; jj < 32; jj++) w2[jj] = Wih2[qq * H + koff + jj];
        whh2q = Whh2[qq];
        b2q   = bih2[qq] + bhh2[qq];
    }
    __syncthreads();

    for (int t = 0; t <= T; t++) {
        const int wb = t & 1;
        const int rb = wb ^ 1;
        if (is_gate) {
            if (t < T) {
                // ---- B fragments from h(t-1): 16 conflict-free LDS.32 ----
                uint bh[4][2], blo[4][2];
                const __nv_bfloat16* ph = hbh + (rb * 8 + lq) * 72;
                const __nv_bfloat16* pl = hbl + (rb * 8 + lq) * 72;
                #pragma unroll
                for (int kt = 0; kt < 4; kt++) {
                    bh[kt][0]  = *(const uint*)(ph + kt * 16 + 2 * m);
                    bh[kt][1]  = *(const uint*)(ph + kt * 16 + 2 * m + 8);
                    blo[kt][0] = *(const uint*)(pl + kt * 16 + 2 * m);
                    blo[kt][1] = *(const uint*)(pl + kt * 16 + 2 * m + 8);
                }
                // ---- three independent accumulator sets (depth-4 chains) ----
                float xb0 = 0.f, xb1 = 0.f;
                if (real) { xb0 = xs[t * NB + 2 * m]; xb1 = xs[t * NB + 2 * m + 1]; }
                float C1[4][4], C2[4][4], C3[4][4];
                #pragma unroll
                for (int q = 0; q < 4; q++) {
                    C1[q][0] = fmaf(wiA[q][0], xb0, bsA[q][0]);
                    C1[q][1] = fmaf(wiA[q][0], xb1, bsA[q][0]);
                    C1[q][2] = fmaf(wiA[q][1], xb0, bsA[q][1]);
                    C1[q][3] = fmaf(wiA[q][1], xb1, bsA[q][1]);
                    C2[q][0] = C2[q][1] = C2[q][2] = C2[q][3] = 0.f;
                    C3[q][0] = C3[q][1] = C3[q][2] = C3[q][3] = 0.f;
                }
                // ---- 48 HMMA, 12 independent chains interleaved ----
                #pragma unroll
                for (int kt = 0; kt < 4; kt++) {
                    #pragma unroll
                    for (int q = 0; q < 4; q++) {
                        mma16816(C1[q][0], C1[q][1], C1[q][2], C1[q][3],
                                 Ahi[q][kt][0], Ahi[q][kt][1], Ahi[q][kt][2],
                                 Ahi[q][kt][3], bh[kt][0], bh[kt][1]);
                        mma16816(C2[q][0], C2[q][1], C2[q][2], C2[q][3],
                                 Ahi[q][kt][0], Ahi[q][kt][1], Ahi[q][kt][2],
                                 Ahi[q][kt][3], blo[kt][0], blo[kt][1]);
                        const uint* ap =
                            aloS + ((wid * 4 + q) * 4 + kt) * 4 * 32 + lane;
                        mma16816(C3[q][0], C3[q][1], C3[q][2], C3[q][3],
                                 ap[0], ap[32], ap[64], ap[96],
                                 bh[kt][0], bh[kt][1]);
                    }
                }
                // ---- epilogue: gates of unit u live in this lane ----
                #pragma unroll
                for (int c = 0; c < 4; c++) {
                    float gi = fsigm(C1[0][c] + C2[0][c] + C3[0][c]);
                    float gf = fsigm(C1[1][c] + C2[1][c] + C3[1][c]);
                    float gg = ftanh(C1[2][c] + C2[2][c] + C3[2][c]);
                    float go = fsigm(C1[3][c] + C2[3][c] + C3[3][c]);
                    cst[c] = fmaf(gf, cst[c], gi * gg);
                    float hv = go * ftanh(cst[c]);
                    if (real) {
                        const int u = (c >= 2) ? u1 : u0;
                        const int b = 2 * m + (c & 1);
                        __nv_bfloat16 hh = __float2bfloat16(hv);
                        hbh[(wb * 8 + b) * 72 + u] = hh;
                        hbl[(wb * 8 + b) * 72 + u] =
                            __float2bfloat16(hv - __bfloat162float(hh));
                        c1b[(wb * NB + b) * H + u] = cst[c];
                    }
                }
            }
        } else if (t > 0) {
            // layer 2 consumes c1 of step t-1
            const float* cb = c1b + (((t + 1) & 1) * NB + bl2) * H + koff;
            float4 q0 = *reinterpret_cast<const float4*>(cb + 0);
            float4 q1 = *reinterpret_cast<const float4*>(cb + 4);
            float4 q2 = *reinterpret_cast<const float4*>(cb + 8);
            float4 q3 = *reinterpret_cast<const float4*>(cb + 12);
            float4 q4 = *reinterpret_cast<const float4*>(cb + 16);
            float4 q5 = *reinterpret_cast<const float4*>(cb + 20);
            float4 q6 = *reinterpret_cast<const float4*>(cb + 24);
            float4 q7 = *reinterpret_cast<const float4*>(cb + 28);
            float s =
                q0.x*w2[0]+q0.y*w2[1]+q0.z*w2[2]+q0.w*w2[3]
              + q1.x*w2[4]+q1.y*w2[5]+q1.z*w2[6]+q1.w*w2[7]
              + q2.x*w2[8]+q2.y*w2[9]+q2.z*w2[10]+q2.w*w2[11]
              + q3.x*w2[12]+q3.y*w2[13]+q3.z*w2[14]+q3.w*w2[15]
              + q4.x*w2[16]+q4.y*w2[17]+q4.z*w2[18]+q4.w*w2[19]
              + q5.x*w2[20]+q5.y*w2[21]+q5.z*w2[22]+q5.w*w2[23]
              + q6.x*w2[24]+q6.y*w2[25]+q6.z*w2[26]+q6.w*w2[27]
              + q7.x*w2[28]+q7.y*w2[29]+q7.z*w2[30]+q7.w*w2[31];
            s += __shfl_xor_sync(0xffffffffu, s, 1);
            const float gate = s + b2q + h2v * whh2q;
            const int base = lane & ~7;
            const float gi = __shfl_sync(0xffffffffu, gate, base + 0);
            const float gf = __shfl_sync(0xffffffffu, gate, base + 2);
            const float gg = __shfl_sync(0xffffffffu, gate, base + 4);
            const float go = __shfl_sync(0xffffffffu, gate, base + 6);
            c2v = fsigm(gf) * c2v + fsigm(gi) * ftanh(gg);
            h2v = fsigm(go) * ftanh(c2v);
            if ((lane & 7) == 0)
                out[(b0g + bl2) * T + (t - 1)] = c2v;
        }
        __syncthreads();  // single barrier per step
    }
}

extern "C" void kernel_launch(void* const* d_in, const int* in_sizes, int n_in,
                              void* d_out, int out_size) {
    (void)in_sizes; (void)n_in; (void)out_size;
    cudaFuncSetAttribute(lstm2_kernel,
                         cudaFuncAttributeMaxDynamicSharedMemorySize, SMEM_SZ);
    lstm2_kernel<<<NBLK, NTHR, SMEM_SZ>>>(
        (const float*)d_in[0],  // x
        (const float*)d_in[1],  // Wih1
        (const float*)d_in[2],  // Whh1
        (const float*)d_in[3],  // bih1
        (const float*)d_in[4],  // bhh1
        (const float*)d_in[5],  // Wih2
        (const float*)d_in[6],  // Whh2
        (const float*)d_in[7],  // bih2
        (const float*)d_in[8],  // bhh2
        (float*)d_out);
}